// round 4
// baseline (speedup 1.0000x reference)
#include <cuda_runtime.h>
#include <stdint.h>
#include <math.h>

#define BATCH 8
#define TLEN  512
#define CINT  512
#define CCONT 192
#define CSPK  256
#define DMLP  1536
#define NWIN  1024
#define FRAME 960
#define LTOT  (TLEN*FRAME)   /* 491520 */
#define KOUT  3584           /* 512*7 */

// ---------------- scratch (device globals; no allocation allowed) ----------------
__device__ float d_x[BATCH*CINT*TLEN];      // trunk / residual stream
__device__ float d_h[BATCH*CINT*TLEN];      // dwconv output (pre-LN); reused for final LN(x)
__device__ float d_g[BATCH*DMLP*TLEN];      // pw1+gelu output
__device__ float d_mu[BATCH*TLEN];
__device__ float d_rs[BATCH*TLEN];
__device__ float d_spkadd[BATCH*CINT];
__device__ float d_filt[BATCH*TLEN*NWIN];   // per-frame FIR filters, (b, t, w) w-contig

// ---------------- helpers ----------------
__device__ __forceinline__ uint32_t f2tf32(float x) {
    uint32_t r;
    asm("cvt.rna.tf32.f32 %0, %1;" : "=r"(r) : "f"(x));
    return r;
}
__device__ __forceinline__ void mma_tf32(float c[4], const uint32_t a[4], const uint32_t b[2]) {
    asm volatile("mma.sync.aligned.m16n8k8.row.col.f32.tf32.tf32.f32 "
                 "{%0,%1,%2,%3},{%4,%5,%6,%7},{%8,%9},{%0,%1,%2,%3};"
                 : "+f"(c[0]), "+f"(c[1]), "+f"(c[2]), "+f"(c[3])
                 : "r"(a[0]), "r"(a[1]), "r"(a[2]), "r"(a[3]), "r"(b[0]), "r"(b[1]));
}
__device__ __forceinline__ float gelu_exact(float v) {
    return 0.5f*v*(1.f + erff(v*0.70710678118654752f));
}

// ---------------- spk matvec + bias fold ----------------
__global__ void spk_kernel(const float* __restrict__ w_spk, const float* __restrict__ spk,
                           const float* __restrict__ b_content, const float* __restrict__ b_spk,
                           const float* __restrict__ b_f0, const float* __restrict__ b_energy) {
    int b = blockIdx.x;
    int o = threadIdx.x;
    __shared__ float sv[CSPK];
    if (o < CSPK) sv[o] = spk[b*CSPK + o];
    __syncthreads();
    float acc = 0.f;
    const float* wr = w_spk + (size_t)o*CSPK;
    #pragma unroll 4
    for (int c = 0; c < CSPK; c++) acc += wr[c]*sv[c];
    d_spkadd[b*CINT + o] = acc + b_content[o] + b_spk[o] + b_f0[o] + b_energy[o];
}

// ---------------- trunk GEMM (FFMA; small) ----------------
__global__ void __launch_bounds__(256) gemm_trunk(
    const float* __restrict__ W, const float* __restrict__ content,
    const float* __restrict__ f0, const float* __restrict__ energy,
    const float* __restrict__ wf0, const float* __restrict__ wen) {
    __shared__ float As[8][128];
    __shared__ float Bs[8][128];
    const int tid = threadIdx.x;
    const int b = blockIdx.z;
    const int m0 = blockIdx.x * 128;
    const int t0 = blockIdx.y * 128;
    const int tx = tid & 15, ty = tid >> 4;
    const int am = tid >> 1, ak = (tid & 1) * 4;
    const int bk = tid >> 5, bn = (tid & 31) * 4;
    float acc[8][8];
    #pragma unroll
    for (int i = 0; i < 8; i++)
        #pragma unroll
        for (int j = 0; j < 8; j++) acc[i][j] = 0.f;

    for (int k0 = 0; k0 < CCONT; k0 += 8) {
        float4 av = *(const float4*)(W + (size_t)(m0+am)*CCONT + k0 + ak);
        As[ak+0][am]=av.x; As[ak+1][am]=av.y; As[ak+2][am]=av.z; As[ak+3][am]=av.w;
        float4 bv = *(const float4*)(content + ((size_t)b*CCONT + k0 + bk)*TLEN + t0 + bn);
        *(float4*)&Bs[bk][bn] = bv;
        __syncthreads();
        #pragma unroll
        for (int kk = 0; kk < 8; kk++) {
            float a[8], bb[8];
            #pragma unroll
            for (int i = 0; i < 8; i++) a[i] = As[kk][ty*8+i];
            #pragma unroll
            for (int j = 0; j < 8; j++) bb[j] = Bs[kk][tx*8+j];
            #pragma unroll
            for (int i = 0; i < 8; i++)
                #pragma unroll
                for (int j = 0; j < 8; j++) acc[i][j] += a[i]*bb[j];
        }
        __syncthreads();
    }
    float lf[8], en[8];
    #pragma unroll
    for (int j = 0; j < 8; j++) {
        int t = t0 + tx*8 + j;
        float f = f0[b*TLEN + t];
        lf[j] = logf(fmaxf(f, 0.f) + 1e-6f);
        en[j] = energy[b*TLEN + t];
    }
    #pragma unroll
    for (int i = 0; i < 8; i++) {
        int m = m0 + ty*8 + i;
        float base = d_spkadd[b*CINT + m];
        float wf = wf0[m], we = wen[m];
        float* orow = d_x + ((size_t)b*CINT + m)*TLEN + t0 + tx*8;
        #pragma unroll
        for (int j = 0; j < 8; j++)
            orow[j] = acc[i][j] + base + wf*lf[j] + we*en[j];
    }
}

// ---------------- depthwise conv k=7 zero-pad ----------------
__global__ void dwconv_kernel(const float* __restrict__ w, const float* __restrict__ bias) {
    int t = blockIdx.x*256 + threadIdx.x;
    int c = blockIdx.y, b = blockIdx.z;
    const float* xr = d_x + ((size_t)b*CINT + c)*TLEN;
    float wv[7];
    #pragma unroll
    for (int k = 0; k < 7; k++) wv[k] = w[c*7 + k];
    float acc = bias[c];
    #pragma unroll
    for (int k = 0; k < 7; k++) {
        int tt = t + k - 3;
        if (tt >= 0 && tt < TLEN) acc += xr[tt]*wv[k];
    }
    d_h[((size_t)b*CINT + c)*TLEN + t] = acc;
}

// ---------------- channel-LN statistics (mu, rstd) per (b,t) ----------------
__global__ void stats_kernel(int which) {    // 0 -> d_h, 1 -> d_x
    const float* base = which ? d_x : d_h;
    int b = blockIdx.y;
    int t0 = blockIdx.x * 8;
    int tid = threadIdx.x;
    __shared__ float ssum[8][256];
    __shared__ float ssq[8][256];
    float s[8], q[8];
    #pragma unroll
    for (int j = 0; j < 8; j++) { s[j] = 0.f; q[j] = 0.f; }
    for (int c = tid; c < CINT; c += 256) {
        const float* p = base + ((size_t)b*CINT + c)*TLEN + t0;
        float4 v0 = *(const float4*)p;
        float4 v1 = *(const float4*)(p + 4);
        float v[8] = {v0.x,v0.y,v0.z,v0.w,v1.x,v1.y,v1.z,v1.w};
        #pragma unroll
        for (int j = 0; j < 8; j++) { s[j] += v[j]; q[j] += v[j]*v[j]; }
    }
    #pragma unroll
    for (int j = 0; j < 8; j++) { ssum[j][tid] = s[j]; ssq[j][tid] = q[j]; }
    __syncthreads();
    for (int step = 128; step > 0; step >>= 1) {
        if (tid < step) {
            #pragma unroll
            for (int j = 0; j < 8; j++) {
                ssum[j][tid] += ssum[j][tid+step];
                ssq[j][tid]  += ssq[j][tid+step];
            }
        }
        __syncthreads();
    }
    if (tid < 8) {
        float m = ssum[tid][0] * (1.f/CINT);
        float v = ssq[tid][0] * (1.f/CINT) - m*m;
        d_mu[b*TLEN + t0 + tid] = m;
        d_rs[b*TLEN + t0 + tid] = rsqrtf(v + 1e-6f);
    }
}

// ---------------- materialize final LN(x) into d_h ----------------
__global__ void lnorm_kernel(const float* __restrict__ g, const float* __restrict__ bv) {
    int t = blockIdx.x*256 + threadIdx.x;
    int c = blockIdx.y, b = blockIdx.z;
    float x = d_x[((size_t)b*CINT + c)*TLEN + t];
    d_h[((size_t)b*CINT + c)*TLEN + t] =
        (x - d_mu[b*TLEN + t]) * d_rs[b*TLEN + t] * g[c] + bv[c];
}

// ==================================================================
// TF32 tensor-core GEMMs: 128x128 block, BK=16, 8 warps (2x4), 64x32/warp
// ==================================================================
// pw1: out = gelu(W @ LN(d_h) + bias) -> d_g.  K = CINT.
__global__ void __launch_bounds__(256) gemm_pw1_tc(
    const float* __restrict__ W, const float* __restrict__ bias,
    const float* __restrict__ lng, const float* __restrict__ lnb) {
    __shared__ uint32_t As[16][136];
    __shared__ uint32_t Bs[16][136];
    const int tid = threadIdx.x;
    const int bb = blockIdx.z;
    const int m0 = blockIdx.x * 128;
    const int t0 = blockIdx.y * 128;
    const int warp = tid >> 5, lane = tid & 31;
    const int wm = (warp >> 2) * 64, wn = (warp & 3) * 32;
    const int g = lane >> 2, tg = lane & 3;
    const int am = tid >> 1, akq = (tid & 1) * 8;
    const int bkr = tid >> 4, bn = (tid & 15) * 8;

    float muA[8], rsA[8];
    {
        float4 m0v = *(const float4*)(d_mu + bb*TLEN + t0 + bn);
        float4 m1v = *(const float4*)(d_mu + bb*TLEN + t0 + bn + 4);
        float4 r0v = *(const float4*)(d_rs + bb*TLEN + t0 + bn);
        float4 r1v = *(const float4*)(d_rs + bb*TLEN + t0 + bn + 4);
        muA[0]=m0v.x;muA[1]=m0v.y;muA[2]=m0v.z;muA[3]=m0v.w;
        muA[4]=m1v.x;muA[5]=m1v.y;muA[6]=m1v.z;muA[7]=m1v.w;
        rsA[0]=r0v.x;rsA[1]=r0v.y;rsA[2]=r0v.z;rsA[3]=r0v.w;
        rsA[4]=r1v.x;rsA[5]=r1v.y;rsA[6]=r1v.z;rsA[7]=r1v.w;
    }
    float acc[4][4][4];
    #pragma unroll
    for (int i=0;i<4;i++)
        #pragma unroll
        for (int j=0;j<4;j++)
            #pragma unroll
            for (int k=0;k<4;k++) acc[i][j][k]=0.f;

    for (int k0 = 0; k0 < CINT; k0 += 16) {
        const float* ap = W + (size_t)(m0+am)*CINT + k0 + akq;
        float4 a0 = *(const float4*)ap;
        float4 a1 = *(const float4*)(ap+4);
        As[akq+0][am]=f2tf32(a0.x); As[akq+1][am]=f2tf32(a0.y);
        As[akq+2][am]=f2tf32(a0.z); As[akq+3][am]=f2tf32(a0.w);
        As[akq+4][am]=f2tf32(a1.x); As[akq+5][am]=f2tf32(a1.y);
        As[akq+6][am]=f2tf32(a1.z); As[akq+7][am]=f2tf32(a1.w);
        int c = k0 + bkr;
        const float* hp = d_h + ((size_t)bb*CINT + c)*TLEN + t0 + bn;
        float4 h0 = *(const float4*)hp;
        float4 h1 = *(const float4*)(hp+4);
        float gc = lng[c], bc = lnb[c];
        float hv[8] = {h0.x,h0.y,h0.z,h0.w,h1.x,h1.y,h1.z,h1.w};
        #pragma unroll
        for (int j = 0; j < 8; j++)
            Bs[bkr][bn+j] = f2tf32((hv[j]-muA[j])*rsA[j]*gc + bc);
        __syncthreads();
        #pragma unroll
        for (int kh = 0; kh < 2; kh++) {
            const int kk = kh*8;
            uint32_t afr[4][4], bfr[4][2];
            #pragma unroll
            for (int mf=0; mf<4; mf++) {
                int m = wm + mf*16 + g;
                afr[mf][0] = As[kk+tg][m];
                afr[mf][1] = As[kk+tg][m+8];
                afr[mf][2] = As[kk+tg+4][m];
                afr[mf][3] = As[kk+tg+4][m+8];
            }
            #pragma unroll
            for (int nf=0; nf<4; nf++) {
                int n = wn + nf*8 + g;
                bfr[nf][0] = Bs[kk+tg][n];
                bfr[nf][1] = Bs[kk+tg+4][n];
            }
            #pragma unroll
            for (int mf=0;mf<4;mf++)
                #pragma unroll
                for (int nf=0;nf<4;nf++)
                    mma_tf32(acc[mf][nf], afr[mf], bfr[nf]);
        }
        __syncthreads();
    }
    #pragma unroll
    for (int mf=0;mf<4;mf++) {
        int m = m0 + wm + mf*16 + g;
        float bi0 = bias[m], bi1 = bias[m+8];
        #pragma unroll
        for (int nf=0;nf<4;nf++) {
            int t = t0 + wn + nf*8 + 2*tg;
            float* p0 = d_g + ((size_t)bb*DMLP + m)*TLEN + t;
            float* p1 = d_g + ((size_t)bb*DMLP + m+8)*TLEN + t;
            float2 o0, o1;
            o0.x = gelu_exact(acc[mf][nf][0] + bi0);
            o0.y = gelu_exact(acc[mf][nf][1] + bi0);
            o1.x = gelu_exact(acc[mf][nf][2] + bi1);
            o1.y = gelu_exact(acc[mf][nf][3] + bi1);
            *(float2*)p0 = o0;
            *(float2*)p1 = o1;
        }
    }
}

// pw2: d_x += W @ d_g + bias.  K = DMLP.
__global__ void __launch_bounds__(256) gemm_pw2_tc(
    const float* __restrict__ W, const float* __restrict__ bias) {
    __shared__ uint32_t As[16][136];
    __shared__ uint32_t Bs[16][136];
    const int tid = threadIdx.x;
    const int bb = blockIdx.z;
    const int m0 = blockIdx.x * 128;
    const int t0 = blockIdx.y * 128;
    const int warp = tid >> 5, lane = tid & 31;
    const int wm = (warp >> 2) * 64, wn = (warp & 3) * 32;
    const int g = lane >> 2, tg = lane & 3;
    const int am = tid >> 1, akq = (tid & 1) * 8;
    const int bkr = tid >> 4, bn = (tid & 15) * 8;

    float acc[4][4][4];
    #pragma unroll
    for (int i=0;i<4;i++)
        #pragma unroll
        for (int j=0;j<4;j++)
            #pragma unroll
            for (int k=0;k<4;k++) acc[i][j][k]=0.f;

    for (int k0 = 0; k0 < DMLP; k0 += 16) {
        const float* ap = W + (size_t)(m0+am)*DMLP + k0 + akq;
        float4 a0 = *(const float4*)ap;
        float4 a1 = *(const float4*)(ap+4);
        As[akq+0][am]=f2tf32(a0.x); As[akq+1][am]=f2tf32(a0.y);
        As[akq+2][am]=f2tf32(a0.z); As[akq+3][am]=f2tf32(a0.w);
        As[akq+4][am]=f2tf32(a1.x); As[akq+5][am]=f2tf32(a1.y);
        As[akq+6][am]=f2tf32(a1.z); As[akq+7][am]=f2tf32(a1.w);
        const float* gp = d_g + ((size_t)bb*DMLP + k0 + bkr)*TLEN + t0 + bn;
        float4 h0 = *(const float4*)gp;
        float4 h1 = *(const float4*)(gp+4);
        Bs[bkr][bn+0]=f2tf32(h0.x); Bs[bkr][bn+1]=f2tf32(h0.y);
        Bs[bkr][bn+2]=f2tf32(h0.z); Bs[bkr][bn+3]=f2tf32(h0.w);
        Bs[bkr][bn+4]=f2tf32(h1.x); Bs[bkr][bn+5]=f2tf32(h1.y);
        Bs[bkr][bn+6]=f2tf32(h1.z); Bs[bkr][bn+7]=f2tf32(h1.w);
        __syncthreads();
        #pragma unroll
        for (int kh = 0; kh < 2; kh++) {
            const int kk = kh*8;
            uint32_t afr[4][4], bfr[4][2];
            #pragma unroll
            for (int mf=0; mf<4; mf++) {
                int m = wm + mf*16 + g;
                afr[mf][0] = As[kk+tg][m];
                afr[mf][1] = As[kk+tg][m+8];
                afr[mf][2] = As[kk+tg+4][m];
                afr[mf][3] = As[kk+tg+4][m+8];
            }
            #pragma unroll
            for (int nf=0; nf<4; nf++) {
                int n = wn + nf*8 + g;
                bfr[nf][0] = Bs[kk+tg][n];
                bfr[nf][1] = Bs[kk+tg+4][n];
            }
            #pragma unroll
            for (int mf=0;mf<4;mf++)
                #pragma unroll
                for (int nf=0;nf<4;nf++)
                    mma_tf32(acc[mf][nf], afr[mf], bfr[nf]);
        }
        __syncthreads();
    }
    #pragma unroll
    for (int mf=0;mf<4;mf++) {
        int m = m0 + wm + mf*16 + g;
        float bi0 = bias[m], bi1 = bias[m+8];
        #pragma unroll
        for (int nf=0;nf<4;nf++) {
            int t = t0 + wn + nf*8 + 2*tg;
            float* p0 = d_x + ((size_t)bb*CINT + m)*TLEN + t;
            float* p1 = d_x + ((size_t)bb*CINT + m+8)*TLEN + t;
            float2 r0 = *(float2*)p0;
            float2 r1 = *(float2*)p1;
            r0.x += acc[mf][nf][0] + bi0;
            r0.y += acc[mf][nf][1] + bi0;
            r1.x += acc[mf][nf][2] + bi1;
            r1.y += acc[mf][nf][3] + bi1;
            *(float2*)p0 = r0;
            *(float2*)p1 = r1;
        }
    }
}

// outconv: filt[w,t] = sum_{c,k} Wout[w,c,k] * xn[c, clamp(t+k-3)].  K = 3584.
__global__ void __launch_bounds__(256) gemm_out_tc(
    const float* __restrict__ W, const float* __restrict__ bias) {
    __shared__ uint32_t As[16][136];
    __shared__ uint32_t Bs[16][136];
    const int tid = threadIdx.x;
    const int bb = blockIdx.z;
    const int m0 = blockIdx.x * 128;
    const int t0 = blockIdx.y * 128;
    const int warp = tid >> 5, lane = tid & 31;
    const int wm = (warp >> 2) * 64, wn = (warp & 3) * 32;
    const int g = lane >> 2, tg = lane & 3;
    const int am = tid >> 1, akq = (tid & 1) * 8;
    const int bkr = tid >> 4, bn = (tid & 15) * 8;

    float acc[4][4][4];
    #pragma unroll
    for (int i=0;i<4;i++)
        #pragma unroll
        for (int j=0;j<4;j++)
            #pragma unroll
            for (int k=0;k<4;k++) acc[i][j][k]=0.f;

    for (int k0 = 0; k0 < KOUT; k0 += 16) {
        const float* ap = W + (size_t)(m0+am)*KOUT + k0 + akq;
        float4 a0 = *(const float4*)ap;
        float4 a1 = *(const float4*)(ap+4);
        As[akq+0][am]=f2tf32(a0.x); As[akq+1][am]=f2tf32(a0.y);
        As[akq+2][am]=f2tf32(a0.z); As[akq+3][am]=f2tf32(a0.w);
        As[akq+4][am]=f2tf32(a1.x); As[akq+5][am]=f2tf32(a1.y);
        As[akq+6][am]=f2tf32(a1.z); As[akq+7][am]=f2tf32(a1.w);
        int r = k0 + bkr;
        int c = r / 7;
        int k7 = r - c*7;
        const float* xr = d_h + ((size_t)bb*CINT + c)*TLEN;
        #pragma unroll
        for (int j = 0; j < 8; j++) {
            int t = t0 + bn + j + k7 - 3;
            t = t < 0 ? 0 : (t > TLEN-1 ? TLEN-1 : t);
            Bs[bkr][bn+j] = f2tf32(xr[t]);
        }
        __syncthreads();
        #pragma unroll
        for (int kh = 0; kh < 2; kh++) {
            const int kk = kh*8;
            uint32_t afr[4][4], bfr[4][2];
            #pragma unroll
            for (int mf=0; mf<4; mf++) {
                int m = wm + mf*16 + g;
                afr[mf][0] = As[kk+tg][m];
                afr[mf][1] = As[kk+tg][m+8];
                afr[mf][2] = As[kk+tg+4][m];
                afr[mf][3] = As[kk+tg+4][m+8];
            }
            #pragma unroll
            for (int nf=0; nf<4; nf++) {
                int n = wn + nf*8 + g;
                bfr[nf][0] = Bs[kk+tg][n];
                bfr[nf][1] = Bs[kk+tg+4][n];
            }
            #pragma unroll
            for (int mf=0;mf<4;mf++)
                #pragma unroll
                for (int nf=0;nf<4;nf++)
                    mma_tf32(acc[mf][nf], afr[mf], bfr[nf]);
        }
        __syncthreads();
    }
    #pragma unroll
    for (int mf=0;mf<4;mf++) {
        int w = m0 + wm + mf*16 + g;
        float bw0 = bias[w], bw1 = bias[w+8];
        #pragma unroll
        for (int nf=0;nf<4;nf++) {
            int t = t0 + wn + nf*8 + 2*tg;
            float* base0 = d_filt + ((size_t)(bb*TLEN + t))*NWIN;
            float* base1 = d_filt + ((size_t)(bb*TLEN + t+1))*NWIN;
            base0[w]   = acc[mf][nf][0] + bw0;
            base1[w]   = acc[mf][nf][1] + bw0;
            base0[w+8] = acc[mf][nf][2] + bw1;
            base1[w+8] = acc[mf][nf][3] + bw1;
        }
    }
}

// ---------------- zero output ----------------
__global__ void zero_kernel(float* __restrict__ out) {
    size_t i = ((size_t)blockIdx.x*256 + threadIdx.x)*4;
    *(float4*)(out + i) = make_float4(0.f,0.f,0.f,0.f);
}

// ---------------- per-frame FIR + overlap-add (atomics) ----------------
// block = (frame f, batch b). out_seg[j] = sum_k filt[f,k]*srcpad[j+k], j in [0,1984)
// where srcpad[x] = src[960f + x - 1024] if 0<=x-1024<960 else 0.
// y[960f + j] += out_seg[j].
__global__ void __launch_bounds__(256) fir2_kernel(const float* __restrict__ src,
                                                   float* __restrict__ out) {
    const int f = blockIdx.x;
    const int b = blockIdx.y;
    __shared__ float s_filt[1024];
    __shared__ float s_pad[3464];      // phys = i + (i>>3), i in [0,3072)
    const int tid = threadIdx.x;

    for (int i = tid; i < 3072; i += 256) {
        int i2 = i - 1024;
        float v = 0.f;
        if (i2 >= 0 && i2 < FRAME) v = src[(size_t)b*LTOT + (size_t)f*FRAME + i2];
        s_pad[i + (i >> 3)] = v;
    }
    for (int i = tid; i < 1024; i += 256)
        s_filt[i] = d_filt[((size_t)(b*TLEN + f))*NWIN + i];
    __syncthreads();

    if (tid >= 248) return;
    const int j0 = tid * 8;
    float acc[8];
    #pragma unroll
    for (int r = 0; r < 8; r++) acc[r] = 0.f;

    int p = 9 * (j0 >> 3);             // phys base: (j0+kc) multiple of 8
    for (int kc = 0; kc < 1024; kc += 8) {
        float fk[8];
        #pragma unroll
        for (int q = 0; q < 8; q++) fk[q] = s_filt[kc + q];
        float sv[15];
        #pragma unroll
        for (int q = 0; q < 15; q++) sv[q] = s_pad[p + q + (q >> 3)];
        #pragma unroll
        for (int q = 0; q < 8; q++)
            #pragma unroll
            for (int r = 0; r < 8; r++)
                acc[r] += fk[q] * sv[q + r];
        p += 9;
    }

    const int u0 = f*FRAME + j0;
    #pragma unroll
    for (int r = 0; r < 8; r++) {
        int j = j0 + r;
        int u = u0 + r;
        if (j >= 1 && u < LTOT)
            atomicAdd(out + (size_t)b*LTOT + u, acc[r]);
    }
}

// ---------------- host launcher ----------------
extern "C" void kernel_launch(void* const* d_in, const int* in_sizes, int n_in,
                              void* d_out, int out_size) {
    const float* content  = (const float*)d_in[0];
    const float* f0       = (const float*)d_in[1];
    const float* energy   = (const float*)d_in[2];
    const float* spk      = (const float*)d_in[3];
    const float* source   = (const float*)d_in[4];
    const float* w_content= (const float*)d_in[5];
    const float* b_content= (const float*)d_in[6];
    const float* w_spk    = (const float*)d_in[7];
    const float* b_spk    = (const float*)d_in[8];
    const float* w_f0     = (const float*)d_in[9];
    const float* b_f0     = (const float*)d_in[10];
    const float* w_energy = (const float*)d_in[11];
    const float* b_energy = (const float*)d_in[12];
    const float* dw_w     = (const float*)d_in[13];
    const float* dw_b     = (const float*)d_in[14];
    const float* ln_g     = (const float*)d_in[15];
    const float* ln_b     = (const float*)d_in[16];
    const float* pw1_w    = (const float*)d_in[17];
    const float* pw1_b    = (const float*)d_in[18];
    const float* pw2_w    = (const float*)d_in[19];
    const float* pw2_b    = (const float*)d_in[20];
    const float* out_ln_g = (const float*)d_in[21];
    const float* out_ln_b = (const float*)d_in[22];
    const float* w_out    = (const float*)d_in[23];
    const float* b_out    = (const float*)d_in[24];
    float* out = (float*)d_out;

    zero_kernel<<<BATCH*LTOT/1024, 256>>>(out);
    spk_kernel<<<BATCH, 512>>>(w_spk, spk, b_content, b_spk, b_f0, b_energy);
    gemm_trunk<<<dim3(CINT/128, TLEN/128, BATCH), 256>>>(w_content, content, f0, energy,
                                                         w_f0, w_energy);
    for (int l = 0; l < 6; l++) {
        dwconv_kernel<<<dim3(TLEN/256, CINT, BATCH), 256>>>(dw_w + (size_t)l*CINT*7,
                                                            dw_b + (size_t)l*CINT);
        stats_kernel<<<dim3(TLEN/8, BATCH), 256>>>(0);
        gemm_pw1_tc<<<dim3(DMLP/128, TLEN/128, BATCH), 256>>>(pw1_w + (size_t)l*DMLP*CINT,
                                                              pw1_b + (size_t)l*DMLP,
                                                              ln_g + (size_t)l*CINT,
                                                              ln_b + (size_t)l*CINT);
        gemm_pw2_tc<<<dim3(CINT/128, TLEN/128, BATCH), 256>>>(pw2_w + (size_t)l*CINT*DMLP,
                                                              pw2_b + (size_t)l*CINT);
    }
    stats_kernel<<<dim3(TLEN/8, BATCH), 256>>>(1);
    lnorm_kernel<<<dim3(TLEN/256, CINT, BATCH), 256>>>(out_ln_g, out_ln_b);
    gemm_out_tc<<<dim3(NWIN/128, TLEN/128, BATCH), 256>>>(w_out, b_out);
    fir2_kernel<<<dim3(TLEN, BATCH), 256>>>(source, out);
}

// round 5
// speedup vs baseline: 1.0720x; 1.0720x over previous
#include <cuda_runtime.h>
#include <stdint.h>
#include <math.h>

#define BATCH 8
#define TLEN  512
#define CINT  512
#define CCONT 192
#define CSPK  256
#define DMLP  1536
#define NWIN  1024
#define FRAME 960
#define LTOT  (TLEN*FRAME)   /* 491520 */
#define KOUT  3584           /* 512*7 */

// ---------------- scratch (device globals; no allocation allowed) ----------------
__device__ float d_x[BATCH*CINT*TLEN];
__device__ float d_h[BATCH*CINT*TLEN];
__device__ float d_g[BATCH*DMLP*TLEN];
__device__ float d_mu[BATCH*TLEN];
__device__ float d_rs[BATCH*TLEN];
__device__ float d_spkadd[BATCH*CINT];
__device__ float d_filt[BATCH*TLEN*NWIN];

// ---------------- helpers ----------------
__device__ __forceinline__ uint32_t f2tf32(float x) {
    uint32_t r;
    asm("cvt.rna.tf32.f32 %0, %1;" : "=r"(r) : "f"(x));
    return r;
}
__device__ __forceinline__ void mma_tf32(float c[4], const uint32_t a[4], const uint32_t b[2]) {
    asm volatile("mma.sync.aligned.m16n8k8.row.col.f32.tf32.tf32.f32 "
                 "{%0,%1,%2,%3},{%4,%5,%6,%7},{%8,%9},{%0,%1,%2,%3};"
                 : "+f"(c[0]), "+f"(c[1]), "+f"(c[2]), "+f"(c[3])
                 : "r"(a[0]), "r"(a[1]), "r"(a[2]), "r"(a[3]), "r"(b[0]), "r"(b[1]));
}
__device__ __forceinline__ float gelu_exact(float v) {
    return 0.5f*v*(1.f + erff(v*0.70710678118654752f));
}
__device__ __forceinline__ unsigned long long pk2(float lo, float hi) {
    unsigned long long r;
    asm("mov.b64 %0, {%1, %2};" : "=l"(r) : "f"(lo), "f"(hi));
    return r;
}
__device__ __forceinline__ void fma2(unsigned long long& acc, unsigned long long a,
                                     unsigned long long b) {
    asm("fma.rn.f32x2 %0, %1, %2, %0;" : "+l"(acc) : "l"(a), "l"(b));
}
__device__ __forceinline__ void upk2(float& lo, float& hi, unsigned long long v) {
    asm("mov.b64 {%0, %1}, %2;" : "=f"(lo), "=f"(hi) : "l"(v));
}

// ---------------- spk matvec + bias fold ----------------
__global__ void spk_kernel(const float* __restrict__ w_spk, const float* __restrict__ spk,
                           const float* __restrict__ b_content, const float* __restrict__ b_spk,
                           const float* __restrict__ b_f0, const float* __restrict__ b_energy) {
    int b = blockIdx.x;
    int o = threadIdx.x;
    __shared__ float sv[CSPK];
    if (o < CSPK) sv[o] = spk[b*CSPK + o];
    __syncthreads();
    float acc = 0.f;
    const float* wr = w_spk + (size_t)o*CSPK;
    #pragma unroll 4
    for (int c = 0; c < CSPK; c++) acc += wr[c]*sv[c];
    d_spkadd[b*CINT + o] = acc + b_content[o] + b_spk[o] + b_f0[o] + b_energy[o];
}

// ---------------- trunk GEMM (FFMA; small) ----------------
__global__ void __launch_bounds__(256) gemm_trunk(
    const float* __restrict__ W, const float* __restrict__ content,
    const float* __restrict__ f0, const float* __restrict__ energy,
    const float* __restrict__ wf0, const float* __restrict__ wen) {
    __shared__ float As[8][128];
    __shared__ float Bs[8][128];
    const int tid = threadIdx.x;
    const int b = blockIdx.z;
    const int m0 = blockIdx.x * 128;
    const int t0 = blockIdx.y * 128;
    const int tx = tid & 15, ty = tid >> 4;
    const int am = tid >> 1, ak = (tid & 1) * 4;
    const int bk = tid >> 5, bn = (tid & 31) * 4;
    float acc[8][8];
    #pragma unroll
    for (int i = 0; i < 8; i++)
        #pragma unroll
        for (int j = 0; j < 8; j++) acc[i][j] = 0.f;

    for (int k0 = 0; k0 < CCONT; k0 += 8) {
        float4 av = *(const float4*)(W + (size_t)(m0+am)*CCONT + k0 + ak);
        As[ak+0][am]=av.x; As[ak+1][am]=av.y; As[ak+2][am]=av.z; As[ak+3][am]=av.w;
        float4 bv = *(const float4*)(content + ((size_t)b*CCONT + k0 + bk)*TLEN + t0 + bn);
        *(float4*)&Bs[bk][bn] = bv;
        __syncthreads();
        #pragma unroll
        for (int kk = 0; kk < 8; kk++) {
            float a[8], bb[8];
            #pragma unroll
            for (int i = 0; i < 8; i++) a[i] = As[kk][ty*8+i];
            #pragma unroll
            for (int j = 0; j < 8; j++) bb[j] = Bs[kk][tx*8+j];
            #pragma unroll
            for (int i = 0; i < 8; i++)
                #pragma unroll
                for (int j = 0; j < 8; j++) acc[i][j] += a[i]*bb[j];
        }
        __syncthreads();
    }
    float lf[8], en[8];
    #pragma unroll
    for (int j = 0; j < 8; j++) {
        int t = t0 + tx*8 + j;
        float f = f0[b*TLEN + t];
        lf[j] = logf(fmaxf(f, 0.f) + 1e-6f);
        en[j] = energy[b*TLEN + t];
    }
    #pragma unroll
    for (int i = 0; i < 8; i++) {
        int m = m0 + ty*8 + i;
        float base = d_spkadd[b*CINT + m];
        float wf = wf0[m], we = wen[m];
        float* orow = d_x + ((size_t)b*CINT + m)*TLEN + t0 + tx*8;
        #pragma unroll
        for (int j = 0; j < 8; j++)
            orow[j] = acc[i][j] + base + wf*lf[j] + we*en[j];
    }
}

// ---------------- depthwise conv k=7 zero-pad ----------------
__global__ void dwconv_kernel(const float* __restrict__ w, const float* __restrict__ bias) {
    int t = blockIdx.x*256 + threadIdx.x;
    int c = blockIdx.y, b = blockIdx.z;
    const float* xr = d_x + ((size_t)b*CINT + c)*TLEN;
    float wv[7];
    #pragma unroll
    for (int k = 0; k < 7; k++) wv[k] = w[c*7 + k];
    float acc = bias[c];
    #pragma unroll
    for (int k = 0; k < 7; k++) {
        int tt = t + k - 3;
        if (tt >= 0 && tt < TLEN) acc += xr[tt]*wv[k];
    }
    d_h[((size_t)b*CINT + c)*TLEN + t] = acc;
}

// ---------------- channel-LN statistics ----------------
__global__ void stats_kernel(int which) {    // 0 -> d_h, 1 -> d_x
    const float* base = which ? d_x : d_h;
    int b = blockIdx.y;
    int t0 = blockIdx.x * 8;
    int tid = threadIdx.x;
    __shared__ float ssum[8][256];
    __shared__ float ssq[8][256];
    float s[8], q[8];
    #pragma unroll
    for (int j = 0; j < 8; j++) { s[j] = 0.f; q[j] = 0.f; }
    for (int c = tid; c < CINT; c += 256) {
        const float* p = base + ((size_t)b*CINT + c)*TLEN + t0;
        float4 v0 = *(const float4*)p;
        float4 v1 = *(const float4*)(p + 4);
        float v[8] = {v0.x,v0.y,v0.z,v0.w,v1.x,v1.y,v1.z,v1.w};
        #pragma unroll
        for (int j = 0; j < 8; j++) { s[j] += v[j]; q[j] += v[j]*v[j]; }
    }
    #pragma unroll
    for (int j = 0; j < 8; j++) { ssum[j][tid] = s[j]; ssq[j][tid] = q[j]; }
    __syncthreads();
    for (int step = 128; step > 0; step >>= 1) {
        if (tid < step) {
            #pragma unroll
            for (int j = 0; j < 8; j++) {
                ssum[j][tid] += ssum[j][tid+step];
                ssq[j][tid]  += ssq[j][tid+step];
            }
        }
        __syncthreads();
    }
    if (tid < 8) {
        float m = ssum[tid][0] * (1.f/CINT);
        float v = ssq[tid][0] * (1.f/CINT) - m*m;
        d_mu[b*TLEN + t0 + tid] = m;
        d_rs[b*TLEN + t0 + tid] = rsqrtf(v + 1e-6f);
    }
}

// ---------------- materialize final LN(x) into d_h ----------------
__global__ void lnorm_kernel(const float* __restrict__ g, const float* __restrict__ bv) {
    int t = blockIdx.x*256 + threadIdx.x;
    int c = blockIdx.y, b = blockIdx.z;
    float x = d_x[((size_t)b*CINT + c)*TLEN + t];
    d_h[((size_t)b*CINT + c)*TLEN + t] =
        (x - d_mu[b*TLEN + t]) * d_rs[b*TLEN + t] * g[c] + bv[c];
}

// ==================================================================
// TF32 TC GEMMs, double-buffered: 128x128 tile, BK=16, one sync/iter
// ==================================================================
#define GEMM_DECLS \
    const int tid = threadIdx.x; \
    const int bb = blockIdx.z; \
    const int m0 = blockIdx.x * 128; \
    const int t0 = blockIdx.y * 128; \
    const int warp = tid >> 5, lane = tid & 31; \
    const int wm = (warp >> 2) * 64, wn = (warp & 3) * 32; \
    const int g = lane >> 2, tg = lane & 3; \
    const int am = tid >> 1, akq = (tid & 1) * 8; \
    const int bkr = tid >> 4, bn = (tid & 15) * 8; \
    float acc[4][4][4]; \
    _Pragma("unroll") \
    for (int i=0;i<4;i++) \
        _Pragma("unroll") \
        for (int j=0;j<4;j++) \
            _Pragma("unroll") \
            for (int k=0;k<4;k++) acc[i][j][k]=0.f;

#define GEMM_COMPUTE(B_) { \
    _Pragma("unroll") \
    for (int kh = 0; kh < 2; kh++) { \
        const int kk = kh*8; \
        uint32_t afr[4][4], bfr[4][2]; \
        _Pragma("unroll") \
        for (int mf=0; mf<4; mf++) { \
            int m = wm + mf*16 + g; \
            afr[mf][0] = As[B_][kk+tg][m]; \
            afr[mf][1] = As[B_][kk+tg][m+8]; \
            afr[mf][2] = As[B_][kk+tg+4][m]; \
            afr[mf][3] = As[B_][kk+tg+4][m+8]; \
        } \
        _Pragma("unroll") \
        for (int nf=0; nf<4; nf++) { \
            int n = wn + nf*8 + g; \
            bfr[nf][0] = Bs[B_][kk+tg][n]; \
            bfr[nf][1] = Bs[B_][kk+tg+4][n]; \
        } \
        _Pragma("unroll") \
        for (int mf=0;mf<4;mf++) \
            _Pragma("unroll") \
            for (int nf=0;nf<4;nf++) \
                mma_tf32(acc[mf][nf], afr[mf], bfr[nf]); \
    } }

#define STORE_A(B_) { \
    As[B_][akq+0][am]=f2tf32(ra0.x); As[B_][akq+1][am]=f2tf32(ra0.y); \
    As[B_][akq+2][am]=f2tf32(ra0.z); As[B_][akq+3][am]=f2tf32(ra0.w); \
    As[B_][akq+4][am]=f2tf32(ra1.x); As[B_][akq+5][am]=f2tf32(ra1.y); \
    As[B_][akq+6][am]=f2tf32(ra1.z); As[B_][akq+7][am]=f2tf32(ra1.w); }

// ---------- pw1: d_g = gelu(W @ LN(d_h) + bias) ----------
__global__ void __launch_bounds__(256) gemm_pw1_tc(
    const float* __restrict__ W, const float* __restrict__ bias,
    const float* __restrict__ lng, const float* __restrict__ lnb) {
    __shared__ uint32_t As[2][16][136];
    __shared__ uint32_t Bs[2][16][136];
    GEMM_DECLS
    float muA[8], rsA[8];
    {
        float4 m0v = *(const float4*)(d_mu + bb*TLEN + t0 + bn);
        float4 m1v = *(const float4*)(d_mu + bb*TLEN + t0 + bn + 4);
        float4 r0v = *(const float4*)(d_rs + bb*TLEN + t0 + bn);
        float4 r1v = *(const float4*)(d_rs + bb*TLEN + t0 + bn + 4);
        muA[0]=m0v.x;muA[1]=m0v.y;muA[2]=m0v.z;muA[3]=m0v.w;
        muA[4]=m1v.x;muA[5]=m1v.y;muA[6]=m1v.z;muA[7]=m1v.w;
        rsA[0]=r0v.x;rsA[1]=r0v.y;rsA[2]=r0v.z;rsA[3]=r0v.w;
        rsA[4]=r1v.x;rsA[5]=r1v.y;rsA[6]=r1v.z;rsA[7]=r1v.w;
    }
    float4 ra0, ra1, rb0, rb1;
    float rgc, rbc;

#define PW1_LOAD(K0) { \
    const float* ap = W + (size_t)(m0+am)*CINT + (K0) + akq; \
    ra0 = *(const float4*)ap; ra1 = *(const float4*)(ap+4); \
    int c = (K0) + bkr; \
    const float* hp = d_h + ((size_t)bb*CINT + c)*TLEN + t0 + bn; \
    rb0 = *(const float4*)hp; rb1 = *(const float4*)(hp+4); \
    rgc = lng[c]; rbc = lnb[c]; }

#define PW1_STORE(B_) { \
    STORE_A(B_) \
    float hv[8] = {rb0.x,rb0.y,rb0.z,rb0.w,rb1.x,rb1.y,rb1.z,rb1.w}; \
    _Pragma("unroll") \
    for (int j = 0; j < 8; j++) \
        Bs[B_][bkr][bn+j] = f2tf32((hv[j]-muA[j])*rsA[j]*rgc + rbc); }

    PW1_LOAD(0)
    PW1_STORE(0)
    __syncthreads();
    int buf = 0;
    #pragma unroll 1
    for (int k0 = 16; k0 < CINT; k0 += 16) {
        PW1_LOAD(k0)
        GEMM_COMPUTE(buf)
        PW1_STORE(buf^1)
        __syncthreads();
        buf ^= 1;
    }
    GEMM_COMPUTE(buf)

    #pragma unroll
    for (int mf=0;mf<4;mf++) {
        int m = m0 + wm + mf*16 + g;
        float bi0 = bias[m], bi1 = bias[m+8];
        #pragma unroll
        for (int nf=0;nf<4;nf++) {
            int t = t0 + wn + nf*8 + 2*tg;
            float* p0 = d_g + ((size_t)bb*DMLP + m)*TLEN + t;
            float* p1 = d_g + ((size_t)bb*DMLP + m+8)*TLEN + t;
            float2 o0, o1;
            o0.x = gelu_exact(acc[mf][nf][0] + bi0);
            o0.y = gelu_exact(acc[mf][nf][1] + bi0);
            o1.x = gelu_exact(acc[mf][nf][2] + bi1);
            o1.y = gelu_exact(acc[mf][nf][3] + bi1);
            *(float2*)p0 = o0;
            *(float2*)p1 = o1;
        }
    }
}

// ---------- pw2: d_x += W @ d_g + bias ----------
__global__ void __launch_bounds__(256) gemm_pw2_tc(
    const float* __restrict__ W, const float* __restrict__ bias) {
    __shared__ uint32_t As[2][16][136];
    __shared__ uint32_t Bs[2][16][136];
    GEMM_DECLS
    float4 ra0, ra1, rb0, rb1;

#define PW2_LOAD(K0) { \
    const float* ap = W + (size_t)(m0+am)*DMLP + (K0) + akq; \
    ra0 = *(const float4*)ap; ra1 = *(const float4*)(ap+4); \
    const float* gp = d_g + ((size_t)bb*DMLP + (K0) + bkr)*TLEN + t0 + bn; \
    rb0 = *(const float4*)gp; rb1 = *(const float4*)(gp+4); }

#define PW2_STORE(B_) { \
    STORE_A(B_) \
    Bs[B_][bkr][bn+0]=f2tf32(rb0.x); Bs[B_][bkr][bn+1]=f2tf32(rb0.y); \
    Bs[B_][bkr][bn+2]=f2tf32(rb0.z); Bs[B_][bkr][bn+3]=f2tf32(rb0.w); \
    Bs[B_][bkr][bn+4]=f2tf32(rb1.x); Bs[B_][bkr][bn+5]=f2tf32(rb1.y); \
    Bs[B_][bkr][bn+6]=f2tf32(rb1.z); Bs[B_][bkr][bn+7]=f2tf32(rb1.w); }

    PW2_LOAD(0)
    PW2_STORE(0)
    __syncthreads();
    int buf = 0;
    #pragma unroll 1
    for (int k0 = 16; k0 < DMLP; k0 += 16) {
        PW2_LOAD(k0)
        GEMM_COMPUTE(buf)
        PW2_STORE(buf^1)
        __syncthreads();
        buf ^= 1;
    }
    GEMM_COMPUTE(buf)

    #pragma unroll
    for (int mf=0;mf<4;mf++) {
        int m = m0 + wm + mf*16 + g;
        float bi0 = bias[m], bi1 = bias[m+8];
        #pragma unroll
        for (int nf=0;nf<4;nf++) {
            int t = t0 + wn + nf*8 + 2*tg;
            float* p0 = d_x + ((size_t)bb*CINT + m)*TLEN + t;
            float* p1 = d_x + ((size_t)bb*CINT + m+8)*TLEN + t;
            float2 r0 = *(float2*)p0;
            float2 r1 = *(float2*)p1;
            r0.x += acc[mf][nf][0] + bi0;
            r0.y += acc[mf][nf][1] + bi0;
            r1.x += acc[mf][nf][2] + bi1;
            r1.y += acc[mf][nf][3] + bi1;
            *(float2*)p0 = r0;
            *(float2*)p1 = r1;
        }
    }
}

// ---------- outconv: filt = Wout (*) LN(x) (im2col K=3584) ----------
__global__ void __launch_bounds__(256) gemm_out_tc(
    const float* __restrict__ W, const float* __restrict__ bias) {
    __shared__ uint32_t As[2][16][136];
    __shared__ uint32_t Bs[2][16][136];
    GEMM_DECLS
    float4 ra0, ra1;
    float rxv[8];

#define OUT_LOAD(K0) { \
    const float* ap = W + (size_t)(m0+am)*KOUT + (K0) + akq; \
    ra0 = *(const float4*)ap; ra1 = *(const float4*)(ap+4); \
    int r = (K0) + bkr; \
    int c = r / 7; \
    int k7 = r - c*7; \
    const float* xr = d_h + ((size_t)bb*CINT + c)*TLEN; \
    _Pragma("unroll") \
    for (int j = 0; j < 8; j++) { \
        int t = t0 + bn + j + k7 - 3; \
        t = t < 0 ? 0 : (t > TLEN-1 ? TLEN-1 : t); \
        rxv[j] = xr[t]; \
    } }

#define OUT_STORE(B_) { \
    STORE_A(B_) \
    _Pragma("unroll") \
    for (int j = 0; j < 8; j++) Bs[B_][bkr][bn+j] = f2tf32(rxv[j]); }

    OUT_LOAD(0)
    OUT_STORE(0)
    __syncthreads();
    int buf = 0;
    #pragma unroll 1
    for (int k0 = 16; k0 < KOUT; k0 += 16) {
        OUT_LOAD(k0)
        GEMM_COMPUTE(buf)
        OUT_STORE(buf^1)
        __syncthreads();
        buf ^= 1;
    }
    GEMM_COMPUTE(buf)

    #pragma unroll
    for (int mf=0;mf<4;mf++) {
        int w = m0 + wm + mf*16 + g;
        float bw0 = bias[w], bw1 = bias[w+8];
        #pragma unroll
        for (int nf=0;nf<4;nf++) {
            int t = t0 + wn + nf*8 + 2*tg;
            float* base0 = d_filt + ((size_t)(bb*TLEN + t))*NWIN;
            float* base1 = d_filt + ((size_t)(bb*TLEN + t+1))*NWIN;
            base0[w]   = acc[mf][nf][0] + bw0;
            base1[w]   = acc[mf][nf][1] + bw0;
            base0[w+8] = acc[mf][nf][2] + bw1;
            base1[w+8] = acc[mf][nf][3] + bw1;
        }
    }
}

// ---------------- zero output ----------------
__global__ void zero_kernel(float* __restrict__ out) {
    size_t i = ((size_t)blockIdx.x*256 + threadIdx.x)*4;
    *(float4*)(out + i) = make_float4(0.f,0.f,0.f,0.f);
}

// ---------------- per-frame FIR + overlap-add, f32x2 packed FMA ----------------
__global__ void __launch_bounds__(256) fir3_kernel(const float* __restrict__ src,
                                                   float* __restrict__ out) {
    const int f = blockIdx.x;
    const int b = blockIdx.y;
    __shared__ float s_filt[1024];
    __shared__ float s_pad[3088];
    const int tid = threadIdx.x;

    for (int i = tid; i < 3072; i += 256) {
        int i2 = i - 1024;
        float v = 0.f;
        if (i2 >= 0 && i2 < FRAME) v = src[(size_t)b*LTOT + (size_t)f*FRAME + i2];
        s_pad[i] = v;
    }
    for (int i = tid; i < 1024; i += 256)
        s_filt[i] = d_filt[((size_t)(b*TLEN + f))*NWIN + i];
    __syncthreads();

    if (tid >= 248) return;
    const int j0 = tid * 8;
    unsigned long long accp[4];
    #pragma unroll
    for (int r2 = 0; r2 < 4; r2++) accp[r2] = 0ull;

    #pragma unroll 1
    for (int kc = 0; kc < 1024; kc += 8) {
        float4 fk0 = *(const float4*)&s_filt[kc];
        float4 fk1 = *(const float4*)&s_filt[kc+4];
        const float* sp = &s_pad[j0 + kc];
        float4 s0 = *(const float4*)sp;
        float4 s1 = *(const float4*)(sp+4);
        float4 s2 = *(const float4*)(sp+8);
        float4 s3 = *(const float4*)(sp+12);
        float sv[16] = {s0.x,s0.y,s0.z,s0.w, s1.x,s1.y,s1.z,s1.w,
                        s2.x,s2.y,s2.z,s2.w, s3.x,s3.y,s3.z,s3.w};
        float fk[8] = {fk0.x,fk0.y,fk0.z,fk0.w, fk1.x,fk1.y,fk1.z,fk1.w};
        unsigned long long Ap[7], Bp[7], fkp[8];
        #pragma unroll
        for (int i = 0; i < 7; i++) {
            Ap[i] = pk2(sv[2*i],   sv[2*i+1]);
            Bp[i] = pk2(sv[2*i+1], sv[2*i+2]);
        }
        #pragma unroll
        for (int q = 0; q < 8; q++) fkp[q] = pk2(fk[q], fk[q]);
        #pragma unroll
        for (int q = 0; q < 8; q += 2) {
            #pragma unroll
            for (int r2 = 0; r2 < 4; r2++) fma2(accp[r2], fkp[q],   Ap[q/2 + r2]);
            #pragma unroll
            for (int r2 = 0; r2 < 4; r2++) fma2(accp[r2], fkp[q+1], Bp[q/2 + r2]);
        }
    }

    float accf[8];
    #pragma unroll
    for (int r2 = 0; r2 < 4; r2++) upk2(accf[2*r2], accf[2*r2+1], accp[r2]);

    const int u0 = f*FRAME + j0;
    #pragma unroll
    for (int r = 0; r < 8; r++) {
        int j = j0 + r;
        int u = u0 + r;
        if (j >= 1 && u < LTOT)
            atomicAdd(out + (size_t)b*LTOT + u, accf[r]);
    }
}

// ---------------- host launcher ----------------
extern "C" void kernel_launch(void* const* d_in, const int* in_sizes, int n_in,
                              void* d_out, int out_size) {
    const float* content  = (const float*)d_in[0];
    const float* f0       = (const float*)d_in[1];
    const float* energy   = (const float*)d_in[2];
    const float* spk      = (const float*)d_in[3];
    const float* source   = (const float*)d_in[4];
    const float* w_content= (const float*)d_in[5];
    const float* b_content= (const float*)d_in[6];
    const float* w_spk    = (const float*)d_in[7];
    const float* b_spk    = (const float*)d_in[8];
    const float* w_f0     = (const float*)d_in[9];
    const float* b_f0     = (const float*)d_in[10];
    const float* w_energy = (const float*)d_in[11];
    const float* b_energy = (const float*)d_in[12];
    const float* dw_w     = (const float*)d_in[13];
    const float* dw_b     = (const float*)d_in[14];
    const float* ln_g     = (const float*)d_in[15];
    const float* ln_b     = (const float*)d_in[16];
    const float* pw1_w    = (const float*)d_in[17];
    const float* pw1_b    = (const float*)d_in[18];
    const float* pw2_w    = (const float*)d_in[19];
    const float* pw2_b    = (const float*)d_in[20];
    const float* out_ln_g = (const float*)d_in[21];
    const float* out_ln_b = (const float*)d_in[22];
    const float* w_out    = (const float*)d_in[23];
    const float* b_out    = (const float*)d_in[24];
    float* out = (float*)d_out;

    zero_kernel<<<BATCH*LTOT/1024, 256>>>(out);
    spk_kernel<<<BATCH, 512>>>(w_spk, spk, b_content, b_spk, b_f0, b_energy);
    gemm_trunk<<<dim3(CINT/128, TLEN/128, BATCH), 256>>>(w_content, content, f0, energy,
                                                         w_f0, w_energy);
    for (int l = 0; l < 6; l++) {
        dwconv_kernel<<<dim3(TLEN/256, CINT, BATCH), 256>>>(dw_w + (size_t)l*CINT*7,
                                                            dw_b + (size_t)l*CINT);
        stats_kernel<<<dim3(TLEN/8, BATCH), 256>>>(0);
        gemm_pw1_tc<<<dim3(DMLP/128, TLEN/128, BATCH), 256>>>(pw1_w + (size_t)l*DMLP*CINT,
                                                              pw1_b + (size_t)l*DMLP,
                                                              ln_g + (size_t)l*CINT,
                                                              ln_b + (size_t)l*CINT);
        gemm_pw2_tc<<<dim3(CINT/128, TLEN/128, BATCH), 256>>>(pw2_w + (size_t)l*CINT*DMLP,
                                                              pw2_b + (size_t)l*CINT);
    }
    stats_kernel<<<dim3(TLEN/8, BATCH), 256>>>(1);
    lnorm_kernel<<<dim3(TLEN/256, CINT, BATCH), 256>>>(out_ln_g, out_ln_b);
    gemm_out_tc<<<dim3(NWIN/128, TLEN/128, BATCH), 256>>>(w_out, b_out);
    fir3_kernel<<<dim3(TLEN, BATCH), 256>>>(source, out);
}